// round 3
// baseline (speedup 1.0000x reference)
#include <cuda_runtime.h>
#include <math.h>

typedef unsigned long long ull;

#define NQ 20000
#define KN 32
#define FULLM 0xffffffffu

__device__ float g_hbar[NQ * 64];

// ---------- packed f32x2 helpers ----------
__device__ __forceinline__ ull pk2(float lo, float hi) {
    ull r; asm("mov.b64 %0, {%1, %2};" : "=l"(r) : "f"(lo), "f"(hi)); return r;
}
__device__ __forceinline__ void upk2(ull v, float& lo, float& hi) {
    asm("mov.b64 {%0, %1}, %2;" : "=f"(lo), "=f"(hi) : "l"(v));
}
__device__ __forceinline__ ull fma2(ull a, ull b, ull c) {
    ull d; asm("fma.rn.f32x2 %0, %1, %2, %3;" : "=l"(d) : "l"(a), "l"(b), "l"(c)); return d;
}

// atan2(y, x)/pi for y >= 0; minimax deg-11 odd, err ~1e-6 rad
__device__ __forceinline__ float fast_atan2_pi(float y, float x) {
    float ax = fabsf(x);
    float mx = fmaxf(ax, y);
    float mn = fminf(ax, y);
    float a = __fdividef(mn, fmaxf(mx, 1e-38f));
    float s = a * a;
    float r = -0.01172120f;
    r = fmaf(r, s, 0.05265332f);
    r = fmaf(r, s, -0.11643287f);
    r = fmaf(r, s, 0.19354346f);
    r = fmaf(r, s, -0.33262347f);
    r = fmaf(r, s, 0.99997726f);
    r = r * a;
    r = (y > ax) ? (1.57079632679f - r) : r;
    r = (x < 0.f) ? (3.14159265359f - r) : r;
    return r * 0.31830988618379067f;
}

__device__ __forceinline__ float angle_pi(float axx, float ayy, float azz,
                                          float bxx, float byy, float bzz) {
    float dt = axx * bxx + ayy * byy + azz * bzz;
    float cx = ayy * bzz - azz * byy;
    float cy = azz * bxx - axx * bzz;
    float cz = axx * byy - ayy * bxx;
    float xn = sqrtf(cx * cx + cy * cy + cz * cz);
    return fast_atan2_pi(xn, dt);
}

// ====================== Kernel A: PPF -> L1 -> L2 -> mean ======================
// smem: sW1 256 [j*4+i] | sB1 256..320 | sB2 320..384 | sW2T 384..4736 [i*68+j]
// per-warp hd: 16*34 ull (1088 floats) at 4736 + w*1088
#define A_SW1 0
#define A_SB1 256
#define A_SB2 320
#define A_SW2T 384
#define A_WARP 4736
#define A_SMF (A_WARP + 16 * 1088)

__global__ __launch_bounds__(512, 1)
void ppf_mlp_kernel(const float* __restrict__ q_pts,
                    const float* __restrict__ s_pts,
                    const int* __restrict__ nbr,
                    const float* __restrict__ normals,
                    const float* __restrict__ W1, const float* __restrict__ b1,
                    const float* __restrict__ W2, const float* __restrict__ b2) {
    extern __shared__ float sm[];
    const int tid = threadIdx.x;
    for (int i = tid; i < 256; i += 512) sm[A_SW1 + i] = W1[i];
    for (int i = tid; i < 64; i += 512) { sm[A_SB1 + i] = b1[i]; sm[A_SB2 + i] = b2[i]; }
    for (int l = tid; l < 4096; l += 512) {
        int j = l >> 6, i = l & 63;
        sm[A_SW2T + i * 68 + j] = W2[l];   // W2[j][i] -> [i][j]
    }
    __syncthreads();

    const int w = tid >> 5, lane = tid & 31;
    ull* hd = (ull*)(sm + A_WARP) + w * 544;   // [16][34] ull, dup pairs
    const int j0 = (lane >> 2) * 8;            // 8 j-groups of 8 (4 pairs)
    const int k0 = (lane & 3) * 8;             // 4 k-groups of 8

    for (int q = blockIdx.x * 16 + w; q < NQ; q += 148 * 16) {
        const int idxk = nbr[q * KN + lane];
        const int idx0 = __shfl_sync(FULLM, idxk, 0);

        const float px = q_pts[q * 3 + 0], py = q_pts[q * 3 + 1], pz = q_pts[q * 3 + 2];
        const float pnx = normals[idx0 * 3 + 0], pny = normals[idx0 * 3 + 1], pnz = normals[idx0 * 3 + 2];
        const float sx = s_pts[idxk * 3 + 0], sy = s_pts[idxk * 3 + 1], sz = s_pts[idxk * 3 + 2];
        const float nnx = normals[idxk * 3 + 0], nny = normals[idxk * 3 + 1], nnz = normals[idxk * 3 + 2];

        const float vx = sx - px, vy = sy - py, vz = sz - pz;
        const float dpp = sqrtf(vx * vx + vy * vy + vz * vz);
        const float a1 = angle_pi(pnx, pny, pnz, vx, vy, vz);
        const float a2 = angle_pi(nnx, nny, nnz, vx, vy, vz);
        const float a3 = angle_pi(pnx, pny, pnz, nnx, nny, nnz);

        // acc[jp][kk]: (j0+2jp, j0+2jp+1) pair for k = k0+kk
        ull acc[4][8];
#pragma unroll
        for (int jp = 0; jp < 4; jp++) {
            ull b = *(const ull*)(sm + A_SB2 + j0 + 2 * jp);
#pragma unroll
            for (int kk = 0; kk < 8; kk++) acc[jp][kk] = b;
        }

#pragma unroll
        for (int p = 0; p < 4; p++) {
            // layer1 quarter (16 i), stage as duplicated pairs
            const float4* w1v = (const float4*)(sm + A_SW1) + p * 16;
            const float* b1p = sm + A_SB1 + p * 16;
#pragma unroll
            for (int ii = 0; ii < 16; ii++) {
                float4 wv = w1v[ii];
                float v = b1p[ii];
                v = fmaf(dpp, wv.x, v);
                v = fmaf(a1, wv.y, v);
                v = fmaf(a2, wv.z, v);
                v = fmaf(a3, wv.w, v);
                v = fmaxf(v, 0.f);
                hd[ii * 34 + lane] = pk2(v, v);
            }
            __syncwarp();
#pragma unroll 4
            for (int ii = 0; ii < 16; ii++) {
                const float* wr = sm + A_SW2T + (p * 16 + ii) * 68 + j0;
                ulonglong2 wA = *(const ulonglong2*)wr;         // (j0,j0+1),(j0+2,j0+3)
                ulonglong2 wB = *(const ulonglong2*)(wr + 4);
                const ull* hr = hd + ii * 34 + k0;
                ulonglong2 h01 = *(const ulonglong2*)(hr);
                ulonglong2 h23 = *(const ulonglong2*)(hr + 2);
                ulonglong2 h45 = *(const ulonglong2*)(hr + 4);
                ulonglong2 h67 = *(const ulonglong2*)(hr + 6);
                ull wv2[4] = {wA.x, wA.y, wB.x, wB.y};
                ull hv[8] = {h01.x, h01.y, h23.x, h23.y, h45.x, h45.y, h67.x, h67.y};
#pragma unroll
                for (int jp = 0; jp < 4; jp++)
#pragma unroll
                    for (int kk = 0; kk < 8; kk++)
                        acc[jp][kk] = fma2(wv2[jp], hv[kk], acc[jp][kk]);
            }
            __syncwarp();
        }

        // relu + sum over lane's 8 k, then over the 4 lanes of the k-dimension
        float o8[8];
#pragma unroll
        for (int jp = 0; jp < 4; jp++) {
            float sl = 0.f, sh = 0.f;
#pragma unroll
            for (int kk = 0; kk < 8; kk++) {
                float lo, hi; upk2(acc[jp][kk], lo, hi);
                sl += fmaxf(lo, 0.f);
                sh += fmaxf(hi, 0.f);
            }
            o8[2 * jp] = sl; o8[2 * jp + 1] = sh;
        }
#pragma unroll
        for (int u = 0; u < 8; u++) {
            o8[u] += __shfl_xor_sync(FULLM, o8[u], 1);
            o8[u] += __shfl_xor_sync(FULLM, o8[u], 2);
        }
        if ((lane & 3) == 0) {
            const float inv = 1.f / KN;
            float4* dst = (float4*)(g_hbar + q * 64 + j0);
            dst[0] = make_float4(o8[0] * inv, o8[1] * inv, o8[2] * inv, o8[3] * inv);
            dst[1] = make_float4(o8[4] * inv, o8[5] * inv, o8[6] * inv, o8[7] * inv);
        }
    }
}

// ========= Kernel B: gather-mean + batched L3 + batched gate + Wv GEMM =========
// smem floats:
#define B_W3T 0                   // 64*68  [i*68+o]
#define B_WGT 4352                // 64*196 [j*196+o]
#define B_WVT 16896               // 64*196 [d*196+o]
#define B_BG  29440               // 192
#define B_B3  29632               // 64
#define B_HB  29696               // 64*33 [i*33+q]
#define B_PM  31808               // 64*33 [o*33+q]
#define B_GATE 33920              // 32*196 [q*196+o]
#define B_AGG 40192               // 16 warps * 256 ull (512 floats) q-pairs [d*4+t]
#define B_SMF (B_AGG + 16 * 512)

__global__ __launch_bounds__(512, 1)
void gate_out_kernel(const float* __restrict__ s_feats,
                     const int* __restrict__ nbr,
                     const float* __restrict__ W3, const float* __restrict__ b3,
                     const float* __restrict__ Wg, const float* __restrict__ bg,
                     const float* __restrict__ Wv,
                     float* __restrict__ out) {
    extern __shared__ float sm[];
    const int tid = threadIdx.x;
    for (int l = tid; l < 4096; l += 512) {
        int o = l >> 6, i = l & 63;
        sm[B_W3T + i * 68 + o] = W3[l];
    }
    for (int l = tid; l < 12288; l += 512) {
        int o = l >> 6, j = l & 63;
        sm[B_WGT + j * 196 + o] = Wg[l];
    }
    for (int l = tid; l < 12288; l += 512) {
        int o = l >> 6, d = l & 63;
        sm[B_WVT + d * 196 + o] = Wv[l];
    }
    for (int l = tid; l < 192; l += 512) sm[B_BG + l] = bg[l];
    for (int l = tid; l < 64; l += 512) sm[B_B3 + l] = b3[l];
    __syncthreads();

    const int w = tid >> 5, lane = tid & 31;
    ull* ag = (ull*)(sm + B_AGG) + w * 256;

    for (int base = blockIdx.x * 32; base < NQ; base += 148 * 32) {
        // ---- gather-mean for this warp's 2 queries (w, w+16) ----
        float fa[2][6];
#pragma unroll
        for (int h = 0; h < 2; h++) {
            const int qq = base + w + 16 * h;
            const int ridx = nbr[qq * KN + lane];
            float2 s0 = {0.f, 0.f}, s1 = {0.f, 0.f}, s2 = {0.f, 0.f};
#pragma unroll 4
            for (int k = 0; k < KN; k++) {
                int row = __shfl_sync(FULLM, ridx, k);
                const float2* bb = (const float2*)(s_feats + (size_t)row * 192) + 3 * lane;
                float2 v0 = bb[0], v1 = bb[1], v2 = bb[2];
                s0.x += v0.x; s0.y += v0.y;
                s1.x += v1.x; s1.y += v1.y;
                s2.x += v2.x; s2.y += v2.y;
            }
            const float inv = 1.f / KN;
            fa[h][0] = s0.x * inv; fa[h][1] = s0.y * inv; fa[h][2] = s1.x * inv;
            fa[h][3] = s1.y * inv; fa[h][4] = s2.x * inv; fa[h][5] = s2.y * inv;
        }
        {
            const int d0 = 2 * lane;
            ag[d0 * 4 + 0] = pk2(fa[0][0], fa[1][0]);
            ag[d0 * 4 + 1] = pk2(fa[0][1], fa[1][1]);
            ag[d0 * 4 + 2] = pk2(fa[0][2], fa[1][2]);
            ag[(d0 + 1) * 4 + 0] = pk2(fa[0][3], fa[1][3]);
            ag[(d0 + 1) * 4 + 1] = pk2(fa[0][4], fa[1][4]);
            ag[(d0 + 1) * 4 + 2] = pk2(fa[0][5], fa[1][5]);
        }
        __syncthreads();

        // ---- stage hbar tile [64 i][32 q] ----
        const float* hsrc = g_hbar + (size_t)base * 64;
        for (int e = tid; e < 2048; e += 512) {
            int qq = e >> 6, ii = e & 63;
            sm[B_HB + ii * 33 + qq] = hsrc[e];
        }
        __syncthreads();

        // ---- L3 batched: thread (q = tid&31, og = tid>>5) -> 4 o ----
        {
            const int ql = tid & 31, o4 = (tid >> 5) * 4;
            float c0 = sm[B_B3 + o4 + 0], c1 = sm[B_B3 + o4 + 1];
            float c2 = sm[B_B3 + o4 + 2], c3 = sm[B_B3 + o4 + 3];
#pragma unroll 8
            for (int i = 0; i < 64; i++) {
                float hv = sm[B_HB + i * 33 + ql];
                float4 wv = *(const float4*)(sm + B_W3T + i * 68 + o4);
                c0 = fmaf(hv, wv.x, c0); c1 = fmaf(hv, wv.y, c1);
                c2 = fmaf(hv, wv.z, c2); c3 = fmaf(hv, wv.w, c3);
            }
            sm[B_PM + (o4 + 0) * 33 + ql] = c0;
            sm[B_PM + (o4 + 1) * 33 + ql] = c1;
            sm[B_PM + (o4 + 2) * 33 + ql] = c2;
            sm[B_PM + (o4 + 3) * 33 + ql] = c3;
        }
        __syncthreads();

        // ---- gate batched: thread (q, og) -> 12 o ----
        {
            const int ql = tid & 31, ob = (tid >> 5) * 12;
            ull ga[6];
#pragma unroll
            for (int s = 0; s < 6; s++) ga[s] = *(const ull*)(sm + B_BG + ob + 2 * s);
#pragma unroll 4
            for (int j = 0; j < 64; j++) {
                float pv = sm[B_PM + j * 33 + ql];
                ull pp = pk2(pv, pv);
                const float* wr = sm + B_WGT + j * 196 + ob;
                ulonglong2 wA = *(const ulonglong2*)wr;
                ulonglong2 wB = *(const ulonglong2*)(wr + 4);
                ulonglong2 wC = *(const ulonglong2*)(wr + 8);
                ga[0] = fma2(wA.x, pp, ga[0]); ga[1] = fma2(wA.y, pp, ga[1]);
                ga[2] = fma2(wB.x, pp, ga[2]); ga[3] = fma2(wB.y, pp, ga[3]);
                ga[4] = fma2(wC.x, pp, ga[4]); ga[5] = fma2(wC.y, pp, ga[5]);
            }
            float* gr = sm + B_GATE + ql * 196 + ob;
#pragma unroll
            for (int s = 0; s < 6; s++) {
                float lo, hi; upk2(ga[s], lo, hi);
                gr[2 * s + 0] = __fdividef(1.f, 1.f + __expf(-lo));
                gr[2 * s + 1] = __fdividef(1.f, 1.f + __expf(-hi));
            }
        }
        __syncthreads();

        // ---- Wv GEMM with (q0,q1) packed in f32x2 lanes; gate; store ----
        {
            const int ob = lane * 6;
            ull acc2[6][3];
#pragma unroll
            for (int oo = 0; oo < 6; oo++)
#pragma unroll
                for (int t = 0; t < 3; t++) acc2[oo][t] = 0ull;
#pragma unroll 2
            for (int d = 0; d < 64; d++) {
                const float* wp = sm + B_WVT + d * 196 + ob;
                float2 w01 = *(const float2*)wp;
                float2 w23 = *(const float2*)(wp + 2);
                float2 w45 = *(const float2*)(wp + 4);
                ulonglong2 t01 = *(const ulonglong2*)(ag + d * 4);
                ull t2 = ag[d * 4 + 2];
                float wv6[6] = {w01.x, w01.y, w23.x, w23.y, w45.x, w45.y};
#pragma unroll
                for (int oo = 0; oo < 6; oo++) {
                    ull wd = pk2(wv6[oo], wv6[oo]);
                    acc2[oo][0] = fma2(wd, t01.x, acc2[oo][0]);
                    acc2[oo][1] = fma2(wd, t01.y, acc2[oo][1]);
                    acc2[oo][2] = fma2(wd, t2, acc2[oo][2]);
                }
            }
            float* outr0 = out + (size_t)(base + w) * 576;
            float* outr1 = out + (size_t)(base + w + 16) * 576;
#pragma unroll
            for (int oo = 0; oo < 6; oo++) {
                const int o = ob + oo;
                float g0 = sm[B_GATE + w * 196 + o];
                float g1 = sm[B_GATE + (w + 16) * 196 + o];
                float x0, x1, y0, y1, z0, z1;
                upk2(acc2[oo][0], x0, x1);
                upk2(acc2[oo][1], y0, y1);
                upk2(acc2[oo][2], z0, z1);
                outr0[o * 3 + 0] = x0 * g0;
                outr0[o * 3 + 1] = y0 * g0;
                outr0[o * 3 + 2] = z0 * g0;
                outr1[o * 3 + 0] = x1 * g1;
                outr1[o * 3 + 1] = y1 * g1;
                outr1[o * 3 + 2] = z1 * g1;
            }
        }
        __syncthreads();   // protect sgate/shb/spme before next tile
    }
}

extern "C" void kernel_launch(void* const* d_in, const int* in_sizes, int n_in,
                              void* d_out, int out_size) {
    const float* q_pts   = (const float*)d_in[0];
    const float* s_pts   = (const float*)d_in[1];
    const float* s_feats = (const float*)d_in[2];
    const int*   nbr     = (const int*)  d_in[3];
    const float* normals = (const float*)d_in[4];
    const float* W1 = (const float*)d_in[5];
    const float* b1 = (const float*)d_in[6];
    const float* W2 = (const float*)d_in[7];
    const float* b2 = (const float*)d_in[8];
    const float* W3 = (const float*)d_in[9];
    const float* b3 = (const float*)d_in[10];
    const float* Wg = (const float*)d_in[11];
    const float* bg = (const float*)d_in[12];
    const float* Wv = (const float*)d_in[13];
    float* out = (float*)d_out;

    size_t smemA = A_SMF * sizeof(float);   // ~88.6 KB
    size_t smemB = B_SMF * sizeof(float);   // ~193.5 KB
    cudaFuncSetAttribute(ppf_mlp_kernel,
                         cudaFuncAttributeMaxDynamicSharedMemorySize, (int)smemA);
    cudaFuncSetAttribute(gate_out_kernel,
                         cudaFuncAttributeMaxDynamicSharedMemorySize, (int)smemB);

    ppf_mlp_kernel<<<148, 512, smemA>>>(q_pts, s_pts, nbr, normals, W1, b1, W2, b2);
    gate_out_kernel<<<148, 512, smemB>>>(s_feats, nbr, W3, b3, Wg, bg, Wv, out);
}